// round 11
// baseline (speedup 1.0000x reference)
#include <cuda_runtime.h>
#include <cstdint>
#include <stddef.h>

// Problem constants (match reference_code)
#define NN      16384
#define IN_DIM  64
#define L0      32
#define L1      48
#define L2      64
#define MLP_H   32
#define NCLS    2
#define CAPN    128   // max neighbors per row (Poisson(~33): P(deg>=128) ~ 1e-30)

// ---------------- scratch (__device__ globals; no allocation allowed) ----------
__device__ int   d_nbr[(size_t)NN * CAPN];   // 8 MB  ELL neighbor indices
__device__ int   d_cnt[NN];
__device__ float d_dinv[NN];
__device__ float d_bufA[(size_t)NN * 64];    // 4 MB  ping
__device__ float d_bufB[(size_t)NN * 64];    // 4 MB  pong
__device__ float d_part[512 * 64];           // column partials from gemm3 blocks

// ---------------------------------------------------------------------------
// Kernel 1: stream 1 GiB dense adjacency once; build ELL lists + degrees.
// EXACT form that measured 174.6us (regs 44, occ 56%, DRAM 76%). One warp per
// row; __ldcs streams. Deterministic: fixed traversal + warp exclusive scan.
// ---------------------------------------------------------------------------
__global__ __launch_bounds__(256) void build_sparse(const float* __restrict__ adj) {
    const int warp = blockIdx.x * 8 + (threadIdx.x >> 5);
    const int lane = threadIdx.x & 31;
    const int row  = warp;  // 2048 blocks x 8 warps -> 16384 rows

    const uint4* __restrict__ arow =
        reinterpret_cast<const uint4*>(adj + (size_t)row * NN);

    int loc[32];
    int lc = 0;      // stored candidates (capped at 32)
    int cnt = 0;     // true nonzero count (uncapped)

    #pragma unroll 1
    for (int it = 0; it < 16; it++) {
        const int base = it * 256;
        uint4 v[8];
        #pragma unroll
        for (int u = 0; u < 8; u++)
            v[u] = __ldcs(&arow[base + u * 32 + lane]);
        unsigned o = 0u;
        #pragma unroll
        for (int u = 0; u < 8; u++)
            o |= (v[u].x | v[u].y | v[u].z | v[u].w);
        if (o) {
            #pragma unroll
            for (int u = 0; u < 8; u++) {
                const int c = 4 * (base + u * 32 + lane);
                if (v[u].x) { if (lc < 32) loc[lc++] = c;     cnt++; }
                if (v[u].y) { if (lc < 32) loc[lc++] = c + 1; cnt++; }
                if (v[u].z) { if (lc < 32) loc[lc++] = c + 2; cnt++; }
                if (v[u].w) { if (lc < 32) loc[lc++] = c + 3; cnt++; }
            }
        }
    }
    const int stored = lc;

    const unsigned m = 0xffffffffu;
    int incl = stored;
    #pragma unroll
    for (int d = 1; d < 32; d <<= 1) {
        int nv = __shfl_up_sync(m, incl, d);
        if (lane >= d) incl += nv;
    }
    const int excl = incl - stored;

    int deg = cnt;
    #pragma unroll
    for (int d = 16; d > 0; d >>= 1) deg += __shfl_xor_sync(m, deg, d);

    int* __restrict__ nl = d_nbr + (size_t)row * CAPN;
    for (int t = 0; t < stored; t++) {
        const int p = excl + t;
        if (p < CAPN) nl[p] = loc[t];
    }
    if (lane == 31) {
        const int tot = incl;
        d_cnt[row] = tot < CAPN ? tot : CAPN;
    }
    if (lane == 0)
        d_dinv[row] = rsqrtf((float)deg + 1.0f);   // deg includes self loop
}

// ---------------------------------------------------------------------------
// Kernel 2 (x3): out = epilogue( H @ W ), H tile in shared, W col in registers.
// MODE 0: out = dinv[row] * acc
// MODE 1: out = dinv[row] * relu(acc + bias[tx])
// MODE 2: out = relu(acc + bias[tx])   (+ optional fused column partials)
// ---------------------------------------------------------------------------
template <int KI, int KO, int TPB, int MODE, bool COLSUM>
__global__ __launch_bounds__(TPB) void gemm_scale(const float* __restrict__ H,
                                                  const float* __restrict__ W,
                                                  const float* __restrict__ dinv,
                                                  const float* __restrict__ bias,
                                                  float* __restrict__ out,
                                                  float* __restrict__ part) {
    constexpr int ROWS = 32;
    constexpr int NR   = TPB / KO;          // rows per sweep
    constexpr int RPT  = ROWS / NR;         // rows per thread (=4)
    __shared__ float Hs[ROWS * KI];
    __shared__ float sh[COLSUM ? NR : 1][COLSUM ? KO : 1];

    const int tid  = threadIdx.x;
    const int row0 = blockIdx.x * ROWS;

    const float4* __restrict__ Hg =
        reinterpret_cast<const float4*>(H + (size_t)row0 * KI);
    #pragma unroll
    for (int i = tid; i < ROWS * KI / 4; i += TPB)
        reinterpret_cast<float4*>(Hs)[i] = Hg[i];

    const int tx = tid % KO;
    const int ty = tid / KO;
    float wreg[KI];
    #pragma unroll
    for (int k = 0; k < KI; k++) wreg[k] = __ldg(&W[k * KO + tx]);
    __syncthreads();

    float acc[RPT];
    #pragma unroll
    for (int i = 0; i < RPT; i++) acc[i] = 0.f;

    #pragma unroll
    for (int k4 = 0; k4 < KI / 4; k4++) {
        #pragma unroll
        for (int i = 0; i < RPT; i++) {
            const float4 h =
                *reinterpret_cast<const float4*>(&Hs[(ty + i * NR) * KI + 4 * k4]);
            acc[i] += h.x * wreg[4 * k4 + 0] + h.y * wreg[4 * k4 + 1]
                    + h.z * wreg[4 * k4 + 2] + h.w * wreg[4 * k4 + 3];
        }
    }

    float csum = 0.f;
    #pragma unroll
    for (int i = 0; i < RPT; i++) {
        const int row = row0 + ty + i * NR;
        float v;
        if (MODE == 0)      v = dinv[row] * acc[i];
        else if (MODE == 1) v = dinv[row] * fmaxf(acc[i] + bias[tx], 0.f);
        else                v = fmaxf(acc[i] + bias[tx], 0.f);
        out[(size_t)row * KO + tx] = v;
        if (COLSUM) csum += v;
    }

    if (COLSUM) {
        sh[ty][tx] = csum;
        __syncthreads();
        if (ty == 0) {
            float s = 0.f;
            #pragma unroll
            for (int q = 0; q < NR; q++) s += sh[q][tx];
            part[blockIdx.x * KO + tx] = s;
        }
    }
}

// ---------------------------------------------------------------------------
// Kernel 3a (KO=32 layers): half-warp float2 gather-aggregate.
// Lanes 0-15 gather even-position neighbors, lanes 16-31 odd-position, each as
// float2 (16 float2 = one 32-float row). Halves the LDG count and doubles
// neighbors-in-flight per batch at UNCHANGED register/occupancy footprint.
// Halves combined by shfl_xor(16); FP add is commutative -> deterministic.
// MODE 0 (X = dinv.(nf@W0)):  out = dinv_i * relu(dinv_i*sum + b)   (= S1)
// MODE 1 (X = S = dinv.h):    out = dinv_i * sum                    (= z)
// ---------------------------------------------------------------------------
template <int MODE>
__global__ __launch_bounds__(256) void spmm_agg32(const float* __restrict__ X,
                                                  const float* __restrict__ bias,
                                                  float* __restrict__ out) {
    const int warp = blockIdx.x * 8 + (threadIdx.x >> 5);
    const int lane = threadIdx.x & 31;
    const int half = lane >> 4;     // 0 or 1
    const int sl   = lane & 15;     // float2 index within row
    const int row  = warp;

    const float2* __restrict__ Xr = reinterpret_cast<const float2*>(X);

    float2 acc0 = make_float2(0.f, 0.f);   // independent chains
    float2 acc1 = make_float2(0.f, 0.f);
    float2 acc2 = make_float2(0.f, 0.f);
    float2 acc3 = make_float2(0.f, 0.f);
    if (half == 0) acc0 = Xr[(size_t)row * 16 + sl];   // self term

    const int n = d_cnt[row];
    const int* __restrict__ nl = d_nbr + (size_t)row * CAPN;

    int k = 0;
    for (; k + 8 <= n; k += 8) {                 // 8 neighbors per batch,
        const int4 ja = *reinterpret_cast<const int4*>(nl + k);      // 4 loads
        const int4 jb = *reinterpret_cast<const int4*>(nl + k + 4);
        const int j0 = half ? ja.y : ja.x;
        const int j1 = half ? ja.w : ja.z;
        const int j2 = half ? jb.y : jb.x;
        const int j3 = half ? jb.w : jb.z;
        const float2 v0 = __ldg(&Xr[(size_t)j0 * 16 + sl]);
        const float2 v1 = __ldg(&Xr[(size_t)j1 * 16 + sl]);
        const float2 v2 = __ldg(&Xr[(size_t)j2 * 16 + sl]);
        const float2 v3 = __ldg(&Xr[(size_t)j3 * 16 + sl]);
        acc0.x += v0.x; acc0.y += v0.y;
        acc1.x += v1.x; acc1.y += v1.y;
        acc2.x += v2.x; acc2.y += v2.y;
        acc3.x += v3.x; acc3.y += v3.y;
    }
    for (; k + 4 <= n; k += 4) {                 // 4 neighbors, 2 loads
        const int4 ja = *reinterpret_cast<const int4*>(nl + k);
        const int j0 = half ? ja.y : ja.x;
        const int j1 = half ? ja.w : ja.z;
        const float2 v0 = __ldg(&Xr[(size_t)j0 * 16 + sl]);
        const float2 v1 = __ldg(&Xr[(size_t)j1 * 16 + sl]);
        acc0.x += v0.x; acc0.y += v0.y;
        acc1.x += v1.x; acc1.y += v1.y;
    }
    for (; k < n; k += 2) {                      // tail: pair across halves
        if (k + half < n) {
            const int j = nl[k + half];
            const float2 v = __ldg(&Xr[(size_t)j * 16 + sl]);
            acc0.x += v.x; acc0.y += v.y;
        }
    }

    float sx = (acc0.x + acc1.x) + (acc2.x + acc3.x);
    float sy = (acc0.y + acc1.y) + (acc2.y + acc3.y);
    const unsigned m = 0xffffffffu;
    sx += __shfl_xor_sync(m, sx, 16);            // commutative -> both halves equal
    sy += __shfl_xor_sync(m, sy, 16);

    if (half == 0) {
        const float di = d_dinv[row];
        float2 o;
        if (MODE == 0) {
            const float2 b = *reinterpret_cast<const float2*>(bias + 2 * sl);
            o.x = di * fmaxf(di * sx + b.x, 0.f);
            o.y = di * fmaxf(di * sy + b.y, 0.f);
        } else {
            o.x = di * sx;
            o.y = di * sy;
        }
        reinterpret_cast<float2*>(out)[(size_t)row * 16 + sl] = o;
    }
}

// ---------------------------------------------------------------------------
// Kernel 3b (KO=48): EXACT 4-deep/dual-accumulator form from the 229.7 best.
// out = dinv_i * sum   (MODE 1 semantics)
// ---------------------------------------------------------------------------
__global__ __launch_bounds__(256) void spmm_agg48(const float* __restrict__ X,
                                                  float* __restrict__ out) {
    constexpr int KO = 48;
    const int warp = blockIdx.x * 8 + (threadIdx.x >> 5);
    const int lane = threadIdx.x & 31;
    const int row  = warp;

    const float* __restrict__ self = X + (size_t)row * KO;
    float a0 = self[lane];
    float c0 = 0.f;
    float a1 = 0.f, c1 = 0.f;
    const bool has1 = (lane + 32 < KO);
    if (has1) a1 = self[32 + lane];

    const int n = d_cnt[row];
    const int* __restrict__ nl = d_nbr + (size_t)row * CAPN;

    int k = 0;
    for (; k + 4 <= n; k += 4) {
        const int4 jj = *reinterpret_cast<const int4*>(nl + k);
        const float* __restrict__ p0 = X + (size_t)jj.x * KO;
        const float* __restrict__ p1 = X + (size_t)jj.y * KO;
        const float* __restrict__ p2 = X + (size_t)jj.z * KO;
        const float* __restrict__ p3 = X + (size_t)jj.w * KO;
        const float x0 = __ldg(&p0[lane]);
        const float x1 = __ldg(&p1[lane]);
        const float x2 = __ldg(&p2[lane]);
        const float x3 = __ldg(&p3[lane]);
        a0 += x0; c0 += x1; a0 += x2; c0 += x3;
        if (has1) {
            const float y0 = __ldg(&p0[32 + lane]);
            const float y1 = __ldg(&p1[32 + lane]);
            const float y2 = __ldg(&p2[32 + lane]);
            const float y3 = __ldg(&p3[32 + lane]);
            a1 += y0; c1 += y1; a1 += y2; c1 += y3;
        }
    }
    for (; k < n; k++) {
        const int j = nl[k];
        const float* __restrict__ p = X + (size_t)j * KO;
        a0 += __ldg(&p[lane]);
        if (has1) a1 += __ldg(&p[32 + lane]);
    }

    const float di = d_dinv[row];
    out[(size_t)row * KO + lane] = di * (a0 + c0);
    if (has1)
        out[(size_t)row * KO + 32 + lane] = di * (a1 + c1);
}

// ---------------------------------------------------------------------------
// Kernel 4: finish mean (512x64 partials), MLP head (elu), logits, softmax.
// ---------------------------------------------------------------------------
__global__ void head(const float* __restrict__ part,
                     const float* __restrict__ Wh1, const float* __restrict__ bh1,
                     const float* __restrict__ Wh2, const float* __restrict__ bh2,
                     float* __restrict__ out) {
    __shared__ float g[64], h1[32], lg[2];
    const int t = threadIdx.x;  // 64 threads
    float s = 0.f;
    #pragma unroll 4
    for (int b = 0; b < 512; b++) s += part[b * 64 + t];
    g[t] = s * (1.0f / (float)NN);
    __syncthreads();
    if (t < MLP_H) {
        float a = bh1[t];
        #pragma unroll
        for (int k = 0; k < 64; k++) a += g[k] * Wh1[k * MLP_H + t];
        h1[t] = (a > 0.f) ? a : expm1f(a);   // elu, alpha=1
    }
    __syncthreads();
    if (t < NCLS) {
        float a = bh2[t];
        #pragma unroll
        for (int k = 0; k < MLP_H; k++) a += h1[k] * Wh2[k * NCLS + t];
        lg[t] = a;
        out[t] = a;                          // logits
    }
    __syncthreads();
    if (t == 0) {
        const float mx = fmaxf(lg[0], lg[1]);
        const float e0 = expf(lg[0] - mx), e1 = expf(lg[1] - mx);
        const float inv = 1.f / (e0 + e1);
        out[2] = e0 * inv;                   // probs
        out[3] = e1 * inv;
    }
}

// ---------------------------------------------------------------------------
extern "C" void kernel_launch(void* const* d_in, const int* in_sizes, int n_in,
                              void* d_out, int out_size) {
    const float* nf   = (const float*)d_in[0];   // [N, 64]
    const float* adj  = (const float*)d_in[1];   // [N, N]
    const float* W0   = (const float*)d_in[2];   // [64, 32]
    const float* b0   = (const float*)d_in[3];
    const float* W1   = (const float*)d_in[4];   // [32, 48]
    const float* b1   = (const float*)d_in[5];
    const float* W2   = (const float*)d_in[6];   // [48, 64]
    const float* b2   = (const float*)d_in[7];
    const float* Wh1  = (const float*)d_in[8];   // [64, 32]
    const float* bh1  = (const float*)d_in[9];
    const float* Wh2  = (const float*)d_in[10];  // [32, 2]
    const float* bh2  = (const float*)d_in[11];
    float* out = (float*)d_out;

    float *bufA, *bufB, *pt, *dinv;
    cudaGetSymbolAddress((void**)&bufA, d_bufA);
    cudaGetSymbolAddress((void**)&bufB, d_bufB);
    cudaGetSymbolAddress((void**)&pt,   d_part);
    cudaGetSymbolAddress((void**)&dinv, d_dinv);

    // 1 GiB streaming pass (HBM-bound)
    build_sparse<<<NN / 8, 256>>>(adj);

    // layer 1 (multiply-first): X1 = dinv.(nf@W0), then aggregate
    gemm_scale<IN_DIM, L0, 256, 0, false><<<NN / 32, 256>>>(nf, W0, dinv,
                                                            nullptr, bufA, nullptr);
    spmm_agg32<0><<<NN / 8, 256>>>(bufA, b0, bufB);      // bufB = S1 = dinv.h1

    // layer 2 (aggregate-first: gather width 32, then 32->48 GEMM)
    spmm_agg32<1><<<NN / 8, 256>>>(bufB, nullptr, bufA); // z2
    gemm_scale<L0, L1, 384, 1, false><<<NN / 32, 384>>>(bufA, W1, dinv, b1,
                                                        bufB, nullptr);    // S2

    // layer 3 (aggregate-first: gather width 48, then 48->64 GEMM + colsum)
    spmm_agg48<<<NN / 8, 256>>>(bufB, bufA);             // z3
    gemm_scale<L1, L2, 512, 2, true><<<NN / 32, 512>>>(bufA, W2, dinv, b2,
                                                       bufB, pt);  // h3 + partials

    // mean + MLP + softmax
    head<<<1, 64>>>(pt, Wh1, bh1, Wh2, bh2, out);
}

// round 12
// speedup vs baseline: 1.1035x; 1.1035x over previous
#include <cuda_runtime.h>
#include <cstdint>
#include <stddef.h>

// Problem constants (match reference_code)
#define NN      16384
#define IN_DIM  64
#define L0      32
#define L1      48
#define L2      64
#define MLP_H   32
#define NCLS    2
#define CAPN    128   // max neighbors per row (Poisson(~33): P(deg>=128) ~ 1e-30)

// ---------------- scratch (__device__ globals; no allocation allowed) ----------
__device__ int   d_nbr[(size_t)NN * CAPN];   // 8 MB  ELL neighbor indices
__device__ int   d_cnt[NN];
__device__ float d_dinv[NN];
__device__ float d_bufA[(size_t)NN * 64];    // 4 MB  ping
__device__ float d_bufB[(size_t)NN * 64];    // 4 MB  pong
__device__ float d_part[128 * 64];           // column partial sums

// ---------------------------------------------------------------------------
// Kernel 1: stream 1 GiB dense adjacency once; build ELL lists + degrees.
// Identical streaming loop to the 174.6us/76%-DRAM measurement, with ONE
// change: minBlocksPerMultiprocessor=6 caps regs at 42 (was 44) -> 6 resident
// blocks = 48 warps/SM instead of 40. More warps = better DRAM busy% + tail
// hiding on a memory-bound kernel (the direction that has won all session).
// Deterministic: fixed traversal + warp exclusive scan (no atomics).
// ---------------------------------------------------------------------------
__global__ __launch_bounds__(256, 6) void build_sparse(const float* __restrict__ adj) {
    const int warp = blockIdx.x * 8 + (threadIdx.x >> 5);
    const int lane = threadIdx.x & 31;
    const int row  = warp;  // 2048 blocks x 8 warps -> 16384 rows

    const uint4* __restrict__ arow =
        reinterpret_cast<const uint4*>(adj + (size_t)row * NN);

    int loc[32];
    int lc = 0;      // stored candidates (capped at 32)
    int cnt = 0;     // true nonzero count (uncapped)

    #pragma unroll 1
    for (int it = 0; it < 16; it++) {
        const int base = it * 256;
        uint4 v[8];
        #pragma unroll
        for (int u = 0; u < 8; u++)
            v[u] = __ldcs(&arow[base + u * 32 + lane]);
        unsigned o = 0u;
        #pragma unroll
        for (int u = 0; u < 8; u++)
            o |= (v[u].x | v[u].y | v[u].z | v[u].w);
        if (o) {
            #pragma unroll
            for (int u = 0; u < 8; u++) {
                const int c = 4 * (base + u * 32 + lane);
                if (v[u].x) { if (lc < 32) loc[lc++] = c;     cnt++; }
                if (v[u].y) { if (lc < 32) loc[lc++] = c + 1; cnt++; }
                if (v[u].z) { if (lc < 32) loc[lc++] = c + 2; cnt++; }
                if (v[u].w) { if (lc < 32) loc[lc++] = c + 3; cnt++; }
            }
        }
    }
    const int stored = lc;

    const unsigned m = 0xffffffffu;
    int incl = stored;
    #pragma unroll
    for (int d = 1; d < 32; d <<= 1) {
        int nv = __shfl_up_sync(m, incl, d);
        if (lane >= d) incl += nv;
    }
    const int excl = incl - stored;

    int deg = cnt;
    #pragma unroll
    for (int d = 16; d > 0; d >>= 1) deg += __shfl_xor_sync(m, deg, d);

    int* __restrict__ nl = d_nbr + (size_t)row * CAPN;
    for (int t = 0; t < stored; t++) {
        const int p = excl + t;
        if (p < CAPN) nl[p] = loc[t];
    }
    if (lane == 31) {
        const int tot = incl;
        d_cnt[row] = tot < CAPN ? tot : CAPN;
    }
    if (lane == 0)
        d_dinv[row] = rsqrtf((float)deg + 1.0f);   // deg includes self loop
}

// ---------------------------------------------------------------------------
// Kernel 2 (x3): out = epilogue( H @ W ), H tile in shared, W col in registers.
// 32 rows/block, RPT=4 independent accumulators, float4 LDS broadcast.
// MODE 0: out = dinv[row] * acc
// MODE 1: out = dinv[row] * relu(acc + bias[tx])
// MODE 2: out = relu(acc + bias[tx])
// ---------------------------------------------------------------------------
template <int KI, int KO, int TPB, int MODE>
__global__ __launch_bounds__(TPB) void gemm_scale(const float* __restrict__ H,
                                                  const float* __restrict__ W,
                                                  const float* __restrict__ dinv,
                                                  const float* __restrict__ bias,
                                                  float* __restrict__ out) {
    constexpr int ROWS = 32;
    constexpr int NR   = TPB / KO;          // rows per sweep
    constexpr int RPT  = ROWS / NR;         // rows per thread (=4)
    __shared__ float Hs[ROWS * KI];

    const int tid  = threadIdx.x;
    const int row0 = blockIdx.x * ROWS;

    const float4* __restrict__ Hg =
        reinterpret_cast<const float4*>(H + (size_t)row0 * KI);
    #pragma unroll
    for (int i = tid; i < ROWS * KI / 4; i += TPB)
        reinterpret_cast<float4*>(Hs)[i] = Hg[i];

    const int tx = tid % KO;
    const int ty = tid / KO;
    float wreg[KI];
    #pragma unroll
    for (int k = 0; k < KI; k++) wreg[k] = __ldg(&W[k * KO + tx]);
    __syncthreads();

    float acc[RPT];
    #pragma unroll
    for (int i = 0; i < RPT; i++) acc[i] = 0.f;

    #pragma unroll
    for (int k4 = 0; k4 < KI / 4; k4++) {
        #pragma unroll
        for (int i = 0; i < RPT; i++) {
            const float4 h =
                *reinterpret_cast<const float4*>(&Hs[(ty + i * NR) * KI + 4 * k4]);
            acc[i] += h.x * wreg[4 * k4 + 0] + h.y * wreg[4 * k4 + 1]
                    + h.z * wreg[4 * k4 + 2] + h.w * wreg[4 * k4 + 3];
        }
    }

    #pragma unroll
    for (int i = 0; i < RPT; i++) {
        const int row = row0 + ty + i * NR;
        float v;
        if (MODE == 0)      v = dinv[row] * acc[i];
        else if (MODE == 1) v = dinv[row] * fmaxf(acc[i] + bias[tx], 0.f);
        else                v = fmaxf(acc[i] + bias[tx], 0.f);
        out[(size_t)row * KO + tx] = v;
    }
}

// ---------------------------------------------------------------------------
// Kernel 3 (x3): gather-aggregate over neighbor lists (L2-resident table).
// EXACT 4-deep/dual-accumulator form from the 229.7us best measurement.
// MODE 0 (X = dinv.(nf@W0)):  out = dinv_i * relu(dinv_i*sum + b)   (= S1)
// MODE 1 (X = S = dinv.h):    out = dinv_i * sum                    (= z)
// ---------------------------------------------------------------------------
template <int KO, int MODE>
__global__ __launch_bounds__(256) void spmm_agg(const float* __restrict__ X,
                                                const float* __restrict__ bias,
                                                float* __restrict__ out) {
    const int warp = blockIdx.x * 8 + (threadIdx.x >> 5);
    const int lane = threadIdx.x & 31;
    const int row  = warp;

    const float* __restrict__ self = X + (size_t)row * KO;
    float a0 = self[lane];
    float c0 = 0.f;
    float a1 = 0.f, c1 = 0.f;
    const bool has1 = (KO > 32) && (lane + 32 < KO);
    if (has1) a1 = self[32 + lane];

    const int n = d_cnt[row];
    const int* __restrict__ nl = d_nbr + (size_t)row * CAPN;

    int k = 0;
    for (; k + 4 <= n; k += 4) {
        const int4 jj = *reinterpret_cast<const int4*>(nl + k);  // uniform bcast
        const float* __restrict__ p0 = X + (size_t)jj.x * KO;
        const float* __restrict__ p1 = X + (size_t)jj.y * KO;
        const float* __restrict__ p2 = X + (size_t)jj.z * KO;
        const float* __restrict__ p3 = X + (size_t)jj.w * KO;
        const float x0 = __ldg(&p0[lane]);
        const float x1 = __ldg(&p1[lane]);
        const float x2 = __ldg(&p2[lane]);
        const float x3 = __ldg(&p3[lane]);
        a0 += x0; c0 += x1; a0 += x2; c0 += x3;
        if (has1) {
            const float y0 = __ldg(&p0[32 + lane]);
            const float y1 = __ldg(&p1[32 + lane]);
            const float y2 = __ldg(&p2[32 + lane]);
            const float y3 = __ldg(&p3[32 + lane]);
            a1 += y0; c1 += y1; a1 += y2; c1 += y3;
        }
    }
    for (; k < n; k++) {
        const int j = nl[k];
        const float* __restrict__ p = X + (size_t)j * KO;
        a0 += __ldg(&p[lane]);
        if (has1) a1 += __ldg(&p[32 + lane]);
    }

    const float di = d_dinv[row];
    const float s0 = a0 + c0;
    if (MODE == 0) {
        out[(size_t)row * KO + lane] = di * fmaxf(di * s0 + bias[lane], 0.f);
        if (has1) {
            const float s1 = a1 + c1;
            out[(size_t)row * KO + 32 + lane] =
                di * fmaxf(di * s1 + bias[32 + lane], 0.f);
        }
    } else {
        out[(size_t)row * KO + lane] = di * s0;
        if (has1)
            out[(size_t)row * KO + 32 + lane] = di * (a1 + c1);
    }
}

// ---------------------------------------------------------------------------
// Kernel 4: column partial sums of H3 (16384 x 64) -> 128 partials per column
// ---------------------------------------------------------------------------
__global__ void colsum(const float* __restrict__ H, float* __restrict__ part) {
    __shared__ float sh[4][64];
    const int col = threadIdx.x;   // 64
    const int ty  = threadIdx.y;   // 4
    const int row0 = blockIdx.x * 128;
    float s = 0.f;
    for (int r = ty; r < 128; r += 4)
        s += H[(size_t)(row0 + r) * 64 + col];
    sh[ty][col] = s;
    __syncthreads();
    if (ty == 0)
        part[blockIdx.x * 64 + col] = sh[0][col] + sh[1][col] + sh[2][col] + sh[3][col];
}

// ---------------------------------------------------------------------------
// Kernel 5: finish mean, MLP head (elu), logits, softmax. Single block, 64 thr.
// ---------------------------------------------------------------------------
__global__ void head(const float* __restrict__ part,
                     const float* __restrict__ Wh1, const float* __restrict__ bh1,
                     const float* __restrict__ Wh2, const float* __restrict__ bh2,
                     float* __restrict__ out) {
    __shared__ float g[64], h1[32], lg[2];
    const int t = threadIdx.x;  // 64 threads
    float s = 0.f;
    for (int b = 0; b < 128; b++) s += part[b * 64 + t];
    g[t] = s * (1.0f / (float)NN);
    __syncthreads();
    if (t < MLP_H) {
        float a = bh1[t];
        #pragma unroll
        for (int k = 0; k < 64; k++) a += g[k] * Wh1[k * MLP_H + t];
        h1[t] = (a > 0.f) ? a : expm1f(a);   // elu, alpha=1
    }
    __syncthreads();
    if (t < NCLS) {
        float a = bh2[t];
        #pragma unroll
        for (int k = 0; k < MLP_H; k++) a += h1[k] * Wh2[k * NCLS + t];
        lg[t] = a;
        out[t] = a;                          // logits
    }
    __syncthreads();
    if (t == 0) {
        const float mx = fmaxf(lg[0], lg[1]);
        const float e0 = expf(lg[0] - mx), e1 = expf(lg[1] - mx);
        const float inv = 1.f / (e0 + e1);
        out[2] = e0 * inv;                   // probs
        out[3] = e1 * inv;
    }
}

// ---------------------------------------------------------------------------
extern "C" void kernel_launch(void* const* d_in, const int* in_sizes, int n_in,
                              void* d_out, int out_size) {
    const float* nf   = (const float*)d_in[0];   // [N, 64]
    const float* adj  = (const float*)d_in[1];   // [N, N]
    const float* W0   = (const float*)d_in[2];   // [64, 32]
    const float* b0   = (const float*)d_in[3];
    const float* W1   = (const float*)d_in[4];   // [32, 48]
    const float* b1   = (const float*)d_in[5];
    const float* W2   = (const float*)d_in[6];   // [48, 64]
    const float* b2   = (const float*)d_in[7];
    const float* Wh1  = (const float*)d_in[8];   // [64, 32]
    const float* bh1  = (const float*)d_in[9];
    const float* Wh2  = (const float*)d_in[10];  // [32, 2]
    const float* bh2  = (const float*)d_in[11];
    float* out = (float*)d_out;

    float *bufA, *bufB, *pt, *dinv;
    cudaGetSymbolAddress((void**)&bufA, d_bufA);
    cudaGetSymbolAddress((void**)&bufB, d_bufB);
    cudaGetSymbolAddress((void**)&pt,   d_part);
    cudaGetSymbolAddress((void**)&dinv, d_dinv);

    // 1) sparse extraction (1 GiB streaming pass; HBM-bound, occ-bumped)
    build_sparse<<<NN / 8, 256>>>(adj);

    // 2) layer 1 (multiply-first: in 64 > out 32)
    gemm_scale<IN_DIM, L0, 256, 0><<<NN / 32, 256>>>(nf, W0, dinv, nullptr, bufA);
    spmm_agg<L0, 0><<<NN / 8, 256>>>(bufA, b0, bufB);     // bufB = S1 = dinv.h1

    // 3) layer 2 (aggregate-first: gather on width 32, then 32->48 GEMM)
    spmm_agg<L0, 1><<<NN / 8, 256>>>(bufB, nullptr, bufA);               // z2
    gemm_scale<L0, L1, 384, 1><<<NN / 32, 384>>>(bufA, W1, dinv, b1, bufB); // S2

    // 4) layer 3 (aggregate-first: gather on width 48, then 48->64 GEMM)
    spmm_agg<L1, 1><<<NN / 8, 256>>>(bufB, nullptr, bufA);               // z3
    gemm_scale<L1, L2, 512, 2><<<NN / 32, 512>>>(bufA, W2, dinv, b2, bufB); // h3

    // 5) mean-pool + MLP + softmax
    colsum<<<128, dim3(64, 4)>>>(bufB, pt);
    head<<<1, 64>>>(pt, Wh1, bh1, Wh2, bh2, out);
}